// round 1
// baseline (speedup 1.0000x reference)
#include <cuda_runtime.h>
#include <cuda_bf16.h>
#include <cstdint>

// Global accumulators (no allocations allowed).
__device__ double             g_total;
__device__ unsigned long long g_count;

__global__ void init_kernel() {
    g_total = 0.0;
    g_count = 0ull;
}

// One warp per row. Lanes stride float4 across the 512-wide row (4 iters).
// Rows whose label >= num_old are skipped entirely (their embedding row is
// never read), halving HBM traffic for uniform labels.
__global__ __launch_bounds__(256)
void mse_kernel(const float* __restrict__ emb,
                const float* __restrict__ cen,
                const int*   __restrict__ labels,
                const int*   __restrict__ num_old_p,
                int batch)
{
    const int num_old = *num_old_p;

    const int warp_global = (blockIdx.x * blockDim.x + threadIdx.x) >> 5;
    const int lane        = threadIdx.x & 31;

    __shared__ double       s_total;
    __shared__ unsigned int s_count;
    if (threadIdx.x == 0) { s_total = 0.0; s_count = 0u; }
    __syncthreads();

    if (warp_global < batch) {
        const int row   = warp_global;
        const int label = labels[row];
        if (label < num_old) {
            const float4* e = reinterpret_cast<const float4*>(emb) + (size_t)row   * 128;
            const float4* c = reinterpret_cast<const float4*>(cen) + (size_t)label * 128;
            float acc = 0.0f;
            #pragma unroll
            for (int i = 0; i < 4; i++) {
                float4 ev = e[lane + 32 * i];
                float4 cv = c[lane + 32 * i];
                float dx = ev.x - cv.x;
                float dy = ev.y - cv.y;
                float dz = ev.z - cv.z;
                float dw = ev.w - cv.w;
                acc = fmaf(dx, dx, acc);
                acc = fmaf(dy, dy, acc);
                acc = fmaf(dz, dz, acc);
                acc = fmaf(dw, dw, acc);
            }
            // Warp reduce.
            #pragma unroll
            for (int off = 16; off > 0; off >>= 1)
                acc += __shfl_xor_sync(0xFFFFFFFFu, acc, off);

            if (lane == 0) {
                atomicAdd(&s_total, (double)acc * (1.0 / 512.0));
                atomicAdd(&s_count, 1u);
            }
        }
    }
    __syncthreads();
    if (threadIdx.x == 0 && s_count > 0u) {
        atomicAdd(&g_total, s_total);
        atomicAdd(&g_count, (unsigned long long)s_count);
    }
}

__global__ void finalize_kernel(float* __restrict__ out) {
    const double             t = g_total;
    const unsigned long long c = g_count;
    out[0] = (c == 0ull) ? (float)t : (float)(t / (double)c);
}

extern "C" void kernel_launch(void* const* d_in, const int* in_sizes, int n_in,
                              void* d_out, int out_size)
{
    const float* emb       = (const float*)d_in[0];
    const float* cen       = (const float*)d_in[1];
    const int*   labels    = (const int*)d_in[2];
    const int*   num_old_p = (const int*)d_in[3];
    float*       out       = (float*)d_out;

    const int dim   = 512;
    const int batch = in_sizes[0] / dim;   // 65536

    init_kernel<<<1, 1>>>();

    const int warps_per_block = 256 / 32;                      // 8 rows/block
    const int grid = (batch + warps_per_block - 1) / warps_per_block;  // 8192
    mse_kernel<<<grid, 256>>>(emb, cen, labels, num_old_p, batch);

    finalize_kernel<<<1, 1>>>(out);
}